// round 16
// baseline (speedup 1.0000x reference)
#include <cuda_runtime.h>
#include <cuda_bf16.h>

// MoE combine: out[token_idx[r]] += gates[r] * expert_hidden[r]
// CSR-lite buckets -> per-token gather -> single coalesced write.
// R16: converged design (PDL zero + bucket + TPB combine w/ metadata
// prefetch; 128.1 +/- 0.7us across 8 runs). Last untested axis: TPB=8
// (grid 2048, fewer block preludes / wave transitions). Everything
// else byte-identical to R15. Measured conclusions baked in:
//  - DRAM ~77% (6.2TB/s) at BOTH occ=48% and occ=68% -> mixed-stream
//    DRAM efficiency is the binding resource; no launch-bounds cap.
//  - Memset prelude loses cross-replay PDL overlap -> keep zero kernel.
//  - Streaming kernel never writes bulk bookkeeping state (R3/R4).

#define MAX_TOKENS 16384
#define MAX_ROWS   32768
#define CAP        32
#define CTHREADS   256
#define VPT        4   // float4 columns per thread
#define TPB        8   // tokens per combine block (R16: 4 -> 8)

__device__ int g_count[MAX_TOKENS];
__device__ int g_bucket[MAX_TOKENS * CAP];
__device__ int g_ovf_count;
__device__ int g_ovf_rows[MAX_ROWS];

__device__ __forceinline__ void gdc_wait() {
    asm volatile("griddepcontrol.wait;" ::: "memory");
}
__device__ __forceinline__ void gdc_launch_dependents() {
    asm volatile("griddepcontrol.launch_dependents;" ::: "memory");
}

__global__ void zero_counts_kernel(int num_tokens) {
    // Gate stores on predecessor's release (prior replay's combine reads
    // g_count); the launch itself may overlap the predecessor.
    gdc_wait();
    int i = blockIdx.x * blockDim.x + threadIdx.x;
    if (i < num_tokens) g_count[i] = 0;
    if (i == 0) g_ovf_count = 0;
    gdc_launch_dependents();
}

__global__ void bucket_kernel(const int* __restrict__ token_idx, int num_rows) {
    int r = blockIdx.x * blockDim.x + threadIdx.x;
    // Independent DRAM load issued BEFORE waiting on the zero kernel.
    int t = (r < num_rows) ? token_idx[r] : 0;
    gdc_wait();
    if (r < num_rows) {
        int p = atomicAdd(&g_count[t], 1);
        if (p < CAP) {
            g_bucket[t * CAP + p] = r;
        } else {
            int q = atomicAdd(&g_ovf_count, 1);
            g_ovf_rows[q] = r;
        }
    }
    gdc_launch_dependents();
}

// ---------------------------------------------------------------------------
// Streaming core for one token (exact shape: hidden4 == VPT*CTHREADS).
// Predicate-free, MLP-4 back-to-back LDG.128, register accumulators.
// ---------------------------------------------------------------------------
__device__ __forceinline__ void stream_token(int t, int n,
                                             const int*   s_rows,
                                             const float* s_gates,
                                             const float4* __restrict__ eh4,
                                             const int*    __restrict__ token_idx,
                                             const float*  __restrict__ gates,
                                             float4*       __restrict__ out4) {
    const int HIDDEN4 = VPT * CTHREADS;   // 1024 float4 columns
    const int c0 = threadIdx.x;
    const int m  = (n < CAP) ? n : CAP;

    float4 acc[VPT];
    #pragma unroll
    for (int j = 0; j < VPT; j++) acc[j] = make_float4(0.f, 0.f, 0.f, 0.f);

    for (int i = 0; i < m; i++) {
        const long long rb = (long long)s_rows[i] * HIDDEN4;
        const float g = s_gates[i];
        float4 v[VPT];
        #pragma unroll
        for (int j = 0; j < VPT; j++)
            v[j] = __ldcs(&eh4[rb + c0 + j * CTHREADS]);
        #pragma unroll
        for (int j = 0; j < VPT; j++) {
            acc[j].x += g * v[j].x;
            acc[j].y += g * v[j].y;
            acc[j].z += g * v[j].z;
            acc[j].w += g * v[j].w;
        }
    }

    // Exact overflow handling (normally dead: requires a >32-row token).
    if (n > CAP) {
        int q = g_ovf_count;
        for (int jj = 0; jj < q; jj++) {
            int r = g_ovf_rows[jj];
            if (token_idx[r] == t) {
                float g = gates[r];
                long long rb = (long long)r * HIDDEN4;
                #pragma unroll
                for (int j = 0; j < VPT; j++) {
                    float4 v = eh4[rb + c0 + j * CTHREADS];
                    acc[j].x += g * v.x; acc[j].y += g * v.y;
                    acc[j].z += g * v.z; acc[j].w += g * v.w;
                }
            }
        }
    }

    const long long ob = (long long)t * HIDDEN4;
    #pragma unroll
    for (int j = 0; j < VPT; j++)
        __stcs(&out4[ob + c0 + j * CTHREADS], acc[j]);
}

// Combine: TPB tokens per block, double-buffered metadata prefetch.
// Tokens strided: t = blockIdx.x + k * gridDim.x. Natural register
// count (regs~50, occ~48%) — measured faster than forced 6 blocks/SM.
__global__ __launch_bounds__(CTHREADS)
void combine_multi_kernel(const float* __restrict__ expert_hidden,
                          const int*   __restrict__ token_idx,
                          const float* __restrict__ gates,
                          float* __restrict__ out) {
    __shared__ int   s_rows[2][CAP];
    __shared__ float s_gates[2][CAP];
    __shared__ int   s_n[2];

    gdc_wait();

    const int nblock = gridDim.x;
    const int t0 = blockIdx.x;

    // Load metadata for token k=0 directly into buffer 0.
    // Bucket slots >= count hold stale in-range values; never used in math.
    {
        int t = t0;
        if (threadIdx.x == 0) s_n[0] = g_count[t];
        if (threadIdx.x < CAP) {
            int r = g_bucket[t * CAP + threadIdx.x];
            s_rows[0][threadIdx.x]  = r;
            s_gates[0][threadIdx.x] = gates[r];
        }
    }
    __syncthreads();

    const float4* eh4  = reinterpret_cast<const float4*>(expert_hidden);
    float4*       out4 = reinterpret_cast<float4*>(out);

    #pragma unroll
    for (int k = 0; k < TPB; k++) {
        const int buf  = k & 1;
        const int nbuf = buf ^ 1;
        const int t    = t0 + k * nblock;

        // Issue next token's metadata loads NOW (consumed after streaming):
        // their DRAM latency hides under the current token's stream.
        int   pn = 0, pr = 0;
        float pg = 0.f;
        const bool hasnext = (k + 1 < TPB);
        if (hasnext) {
            const int tn = t0 + (k + 1) * nblock;
            if (threadIdx.x == 0) pn = g_count[tn];
            if (threadIdx.x < CAP) {
                pr = g_bucket[tn * CAP + threadIdx.x];
                pg = gates[pr];
            }
        }

        // Stream the current token (the long, bandwidth-bound part).
        stream_token(t, s_n[buf], s_rows[buf], s_gates[buf],
                     eh4, token_idx, gates, out4);

        // Publish prefetched metadata for the next iteration.
        if (hasnext) {
            if (threadIdx.x == 0) s_n[nbuf] = pn;
            if (threadIdx.x < CAP) {
                s_rows[nbuf][threadIdx.x]  = pr;
                s_gates[nbuf][threadIdx.x] = pg;
            }
            __syncthreads();
        }
    }
}

// Generic fallback (any hidden divisible by 4), one token per block.
__global__ __launch_bounds__(CTHREADS)
void combine_generic_kernel(const float* __restrict__ expert_hidden,
                            const int*   __restrict__ token_idx,
                            const float* __restrict__ gates,
                            float* __restrict__ out,
                            int hidden4) {
    const int t = blockIdx.x;
    __shared__ int   s_rows[CAP];
    __shared__ float s_gates[CAP];
    __shared__ int   s_n;

    gdc_wait();

    if (threadIdx.x == 0) s_n = g_count[t];
    __syncthreads();
    const int n = s_n;
    const int m = (n < CAP) ? n : CAP;

    if (threadIdx.x < m) {
        int r = g_bucket[t * CAP + threadIdx.x];
        s_rows[threadIdx.x]  = r;
        s_gates[threadIdx.x] = gates[r];
    }
    __syncthreads();

    const float4* eh4  = reinterpret_cast<const float4*>(expert_hidden);
    float4*       out4 = reinterpret_cast<float4*>(out);

    for (int tile = 0; tile < hidden4; tile += VPT * CTHREADS) {
        int col[VPT];
        bool ok[VPT];
        #pragma unroll
        for (int j = 0; j < VPT; j++) {
            col[j] = tile + threadIdx.x + j * CTHREADS;
            ok[j]  = col[j] < hidden4;
        }
        float4 acc[VPT];
        #pragma unroll
        for (int j = 0; j < VPT; j++) acc[j] = make_float4(0.f, 0.f, 0.f, 0.f);

        for (int i = 0; i < m; i++) {
            const long long rb = (long long)s_rows[i] * hidden4;
            const float g = s_gates[i];
            float4 v[VPT];
            #pragma unroll
            for (int j = 0; j < VPT; j++)
                if (ok[j]) v[j] = __ldcs(&eh4[rb + col[j]]);
            #pragma unroll
            for (int j = 0; j < VPT; j++) {
                if (ok[j]) {
                    acc[j].x += g * v[j].x; acc[j].y += g * v[j].y;
                    acc[j].z += g * v[j].z; acc[j].w += g * v[j].w;
                }
            }
        }

        if (n > CAP) {
            int q = g_ovf_count;
            for (int jj = 0; jj < q; jj++) {
                int r = g_ovf_rows[jj];
                if (token_idx[r] == t) {
                    float g = gates[r];
                    long long rb = (long long)r * hidden4;
                    #pragma unroll
                    for (int j = 0; j < VPT; j++) {
                        if (ok[j]) {
                            float4 v = eh4[rb + col[j]];
                            acc[j].x += g * v.x; acc[j].y += g * v.y;
                            acc[j].z += g * v.z; acc[j].w += g * v.w;
                        }
                    }
                }
            }
        }

        const long long ob = (long long)t * hidden4;
        #pragma unroll
        for (int j = 0; j < VPT; j++)
            if (ok[j]) __stcs(&out4[ob + col[j]], acc[j]);
    }
}

extern "C" void kernel_launch(void* const* d_in, const int* in_sizes, int n_in,
                              void* d_out, int out_size) {
    const float* expert_hidden = (const float*)d_in[0];
    const int*   token_idx     = (const int*)d_in[1];
    const float* gates         = (const float*)d_in[2];
    float*       out           = (float*)d_out;

    const int num_rows   = in_sizes[1];               // 32768
    const int hidden     = in_sizes[0] / num_rows;    // 4096
    const int num_tokens = out_size / hidden;         // 16384
    const int hidden4    = hidden / 4;

    cudaLaunchAttribute pdl_attr[1];
    pdl_attr[0].id = cudaLaunchAttributeProgrammaticStreamSerialization;
    pdl_attr[0].val.programmaticStreamSerializationAllowed = 1;

    // 1) zero counters (PDL: launch overlaps prior replay's tail; stores
    //    gated by gdc_wait inside the kernel).
    {
        cudaLaunchConfig_t cfg = {};
        cfg.gridDim  = dim3((num_tokens + 255) / 256);
        cfg.blockDim = dim3(256);
        cfg.stream   = 0;
        cfg.attrs    = pdl_attr;
        cfg.numAttrs = 1;
        cudaLaunchKernelEx(&cfg, zero_counts_kernel, num_tokens);
    }

    // 2) bucket (PDL after zero)
    {
        cudaLaunchConfig_t cfg = {};
        cfg.gridDim  = dim3((num_rows + 255) / 256);
        cfg.blockDim = dim3(256);
        cfg.stream   = 0;
        cfg.attrs    = pdl_attr;
        cfg.numAttrs = 1;
        cudaLaunchKernelEx(&cfg, bucket_kernel, token_idx, num_rows);
    }

    // 3) combine (PDL after bucket)
    {
        cudaLaunchConfig_t cfg = {};
        cfg.blockDim = dim3(CTHREADS);
        cfg.stream   = 0;
        cfg.attrs    = pdl_attr;
        cfg.numAttrs = 1;
        if (hidden4 == VPT * CTHREADS && (num_tokens % TPB) == 0) {
            cfg.gridDim = dim3(num_tokens / TPB);
            cudaLaunchKernelEx(&cfg, combine_multi_kernel,
                               expert_hidden, token_idx, gates, out);
        } else {
            cfg.gridDim = dim3(num_tokens);
            cudaLaunchKernelEx(&cfg, combine_generic_kernel,
                               expert_hidden, token_idx, gates, out, hidden4);
        }
    }
}

// round 17
// speedup vs baseline: 1.0319x; 1.0319x over previous
#include <cuda_runtime.h>
#include <cuda_bf16.h>

// MoE combine: out[token_idx[r]] += gates[r] * expert_hidden[r]
// CSR-lite buckets -> per-token gather -> single coalesced write.
// R17 FINAL: the measured-optimal configuration (R10/R8 point):
//   PDL zero kernel + PDL bucket (early token_idx load) +
//   combine TPB=4 with double-buffered metadata prefetch,
//   MLP-4 predicate-free streaming loop, natural register count.
// Measured map of the design space (all alternatives regress):
//   TPB: 1->128.5, 4->128.06 (opt), 8->131.6
//   ILP: MLP-4 opt; x2 unroll -> +100us (reg pressure)
//   occ: natural (48%) opt; forced 6 blk/SM (68%) -> +6us, DRAM% DOWN
//   sched: static opt; work-stealing cursor -> +1us
//   prelude: PDL zero kernel opt; memset node loses replay-boundary
//            overlap; streaming kernel must never write bookkeeping.
// Bottleneck: 2:1 read/write mixed DRAM stream at ~6.2TB/s (~77% of
// spec), invariant across occupancy -> no remaining lever; traffic is
// minimal (768MB, each byte touched once).

#define MAX_TOKENS 16384
#define MAX_ROWS   32768
#define CAP        32
#define CTHREADS   256
#define VPT        4   // float4 columns per thread
#define TPB        4   // tokens per combine block (measured optimum)

__device__ int g_count[MAX_TOKENS];
__device__ int g_bucket[MAX_TOKENS * CAP];
__device__ int g_ovf_count;
__device__ int g_ovf_rows[MAX_ROWS];

__device__ __forceinline__ void gdc_wait() {
    asm volatile("griddepcontrol.wait;" ::: "memory");
}
__device__ __forceinline__ void gdc_launch_dependents() {
    asm volatile("griddepcontrol.launch_dependents;" ::: "memory");
}

__global__ void zero_counts_kernel(int num_tokens) {
    // Gate stores on predecessor's release (prior replay's combine reads
    // g_count); the launch itself may overlap the predecessor.
    gdc_wait();
    int i = blockIdx.x * blockDim.x + threadIdx.x;
    if (i < num_tokens) g_count[i] = 0;
    if (i == 0) g_ovf_count = 0;
    gdc_launch_dependents();
}

__global__ void bucket_kernel(const int* __restrict__ token_idx, int num_rows) {
    int r = blockIdx.x * blockDim.x + threadIdx.x;
    // Independent DRAM load issued BEFORE waiting on the zero kernel.
    int t = (r < num_rows) ? token_idx[r] : 0;
    gdc_wait();
    if (r < num_rows) {
        int p = atomicAdd(&g_count[t], 1);
        if (p < CAP) {
            g_bucket[t * CAP + p] = r;
        } else {
            int q = atomicAdd(&g_ovf_count, 1);
            g_ovf_rows[q] = r;
        }
    }
    gdc_launch_dependents();
}

// ---------------------------------------------------------------------------
// Streaming core for one token (exact shape: hidden4 == VPT*CTHREADS).
// Predicate-free, MLP-4 back-to-back LDG.128, register accumulators.
// ---------------------------------------------------------------------------
__device__ __forceinline__ void stream_token(int t, int n,
                                             const int*   s_rows,
                                             const float* s_gates,
                                             const float4* __restrict__ eh4,
                                             const int*    __restrict__ token_idx,
                                             const float*  __restrict__ gates,
                                             float4*       __restrict__ out4) {
    const int HIDDEN4 = VPT * CTHREADS;   // 1024 float4 columns
    const int c0 = threadIdx.x;
    const int m  = (n < CAP) ? n : CAP;

    float4 acc[VPT];
    #pragma unroll
    for (int j = 0; j < VPT; j++) acc[j] = make_float4(0.f, 0.f, 0.f, 0.f);

    for (int i = 0; i < m; i++) {
        const long long rb = (long long)s_rows[i] * HIDDEN4;
        const float g = s_gates[i];
        float4 v[VPT];
        #pragma unroll
        for (int j = 0; j < VPT; j++)
            v[j] = __ldcs(&eh4[rb + c0 + j * CTHREADS]);
        #pragma unroll
        for (int j = 0; j < VPT; j++) {
            acc[j].x += g * v[j].x;
            acc[j].y += g * v[j].y;
            acc[j].z += g * v[j].z;
            acc[j].w += g * v[j].w;
        }
    }

    // Exact overflow handling (normally dead: requires a >32-row token).
    if (n > CAP) {
        int q = g_ovf_count;
        for (int jj = 0; jj < q; jj++) {
            int r = g_ovf_rows[jj];
            if (token_idx[r] == t) {
                float g = gates[r];
                long long rb = (long long)r * HIDDEN4;
                #pragma unroll
                for (int j = 0; j < VPT; j++) {
                    float4 v = eh4[rb + c0 + j * CTHREADS];
                    acc[j].x += g * v.x; acc[j].y += g * v.y;
                    acc[j].z += g * v.z; acc[j].w += g * v.w;
                }
            }
        }
    }

    const long long ob = (long long)t * HIDDEN4;
    #pragma unroll
    for (int j = 0; j < VPT; j++)
        __stcs(&out4[ob + c0 + j * CTHREADS], acc[j]);
}

// Combine: TPB tokens per block, double-buffered metadata prefetch.
// Tokens strided: t = blockIdx.x + k * gridDim.x. Natural register
// count (regs~50, occ~48%) — measured faster than forced 6 blocks/SM.
__global__ __launch_bounds__(CTHREADS)
void combine_multi_kernel(const float* __restrict__ expert_hidden,
                          const int*   __restrict__ token_idx,
                          const float* __restrict__ gates,
                          float* __restrict__ out) {
    __shared__ int   s_rows[2][CAP];
    __shared__ float s_gates[2][CAP];
    __shared__ int   s_n[2];

    gdc_wait();

    const int nblock = gridDim.x;
    const int t0 = blockIdx.x;

    // Load metadata for token k=0 directly into buffer 0.
    // Bucket slots >= count hold stale in-range values; never used in math.
    {
        int t = t0;
        if (threadIdx.x == 0) s_n[0] = g_count[t];
        if (threadIdx.x < CAP) {
            int r = g_bucket[t * CAP + threadIdx.x];
            s_rows[0][threadIdx.x]  = r;
            s_gates[0][threadIdx.x] = gates[r];
        }
    }
    __syncthreads();

    const float4* eh4  = reinterpret_cast<const float4*>(expert_hidden);
    float4*       out4 = reinterpret_cast<float4*>(out);

    #pragma unroll
    for (int k = 0; k < TPB; k++) {
        const int buf  = k & 1;
        const int nbuf = buf ^ 1;
        const int t    = t0 + k * nblock;

        // Issue next token's metadata loads NOW (consumed after streaming):
        // their DRAM latency hides under the current token's stream.
        int   pn = 0, pr = 0;
        float pg = 0.f;
        const bool hasnext = (k + 1 < TPB);
        if (hasnext) {
            const int tn = t0 + (k + 1) * nblock;
            if (threadIdx.x == 0) pn = g_count[tn];
            if (threadIdx.x < CAP) {
                pr = g_bucket[tn * CAP + threadIdx.x];
                pg = gates[pr];
            }
        }

        // Stream the current token (the long, bandwidth-bound part).
        stream_token(t, s_n[buf], s_rows[buf], s_gates[buf],
                     eh4, token_idx, gates, out4);

        // Publish prefetched metadata for the next iteration.
        if (hasnext) {
            if (threadIdx.x == 0) s_n[nbuf] = pn;
            if (threadIdx.x < CAP) {
                s_rows[nbuf][threadIdx.x]  = pr;
                s_gates[nbuf][threadIdx.x] = pg;
            }
            __syncthreads();
        }
    }
}

// Generic fallback (any hidden divisible by 4), one token per block.
__global__ __launch_bounds__(CTHREADS)
void combine_generic_kernel(const float* __restrict__ expert_hidden,
                            const int*   __restrict__ token_idx,
                            const float* __restrict__ gates,
                            float* __restrict__ out,
                            int hidden4) {
    const int t = blockIdx.x;
    __shared__ int   s_rows[CAP];
    __shared__ float s_gates[CAP];
    __shared__ int   s_n;

    gdc_wait();

    if (threadIdx.x == 0) s_n = g_count[t];
    __syncthreads();
    const int n = s_n;
    const int m = (n < CAP) ? n : CAP;

    if (threadIdx.x < m) {
        int r = g_bucket[t * CAP + threadIdx.x];
        s_rows[threadIdx.x]  = r;
        s_gates[threadIdx.x] = gates[r];
    }
    __syncthreads();

    const float4* eh4  = reinterpret_cast<const float4*>(expert_hidden);
    float4*       out4 = reinterpret_cast<float4*>(out);

    for (int tile = 0; tile < hidden4; tile += VPT * CTHREADS) {
        int col[VPT];
        bool ok[VPT];
        #pragma unroll
        for (int j = 0; j < VPT; j++) {
            col[j] = tile + threadIdx.x + j * CTHREADS;
            ok[j]  = col[j] < hidden4;
        }
        float4 acc[VPT];
        #pragma unroll
        for (int j = 0; j < VPT; j++) acc[j] = make_float4(0.f, 0.f, 0.f, 0.f);

        for (int i = 0; i < m; i++) {
            const long long rb = (long long)s_rows[i] * hidden4;
            const float g = s_gates[i];
            float4 v[VPT];
            #pragma unroll
            for (int j = 0; j < VPT; j++)
                if (ok[j]) v[j] = __ldcs(&eh4[rb + col[j]]);
            #pragma unroll
            for (int j = 0; j < VPT; j++) {
                if (ok[j]) {
                    acc[j].x += g * v[j].x; acc[j].y += g * v[j].y;
                    acc[j].z += g * v[j].z; acc[j].w += g * v[j].w;
                }
            }
        }

        if (n > CAP) {
            int q = g_ovf_count;
            for (int jj = 0; jj < q; jj++) {
                int r = g_ovf_rows[jj];
                if (token_idx[r] == t) {
                    float g = gates[r];
                    long long rb = (long long)r * hidden4;
                    #pragma unroll
                    for (int j = 0; j < VPT; j++) {
                        if (ok[j]) {
                            float4 v = eh4[rb + col[j]];
                            acc[j].x += g * v.x; acc[j].y += g * v.y;
                            acc[j].z += g * v.z; acc[j].w += g * v.w;
                        }
                    }
                }
            }
        }

        const long long ob = (long long)t * hidden4;
        #pragma unroll
        for (int j = 0; j < VPT; j++)
            if (ok[j]) __stcs(&out4[ob + col[j]], acc[j]);
    }
}

extern "C" void kernel_launch(void* const* d_in, const int* in_sizes, int n_in,
                              void* d_out, int out_size) {
    const float* expert_hidden = (const float*)d_in[0];
    const int*   token_idx     = (const int*)d_in[1];
    const float* gates         = (const float*)d_in[2];
    float*       out           = (float*)d_out;

    const int num_rows   = in_sizes[1];               // 32768
    const int hidden     = in_sizes[0] / num_rows;    // 4096
    const int num_tokens = out_size / hidden;         // 16384
    const int hidden4    = hidden / 4;

    cudaLaunchAttribute pdl_attr[1];
    pdl_attr[0].id = cudaLaunchAttributeProgrammaticStreamSerialization;
    pdl_attr[0].val.programmaticStreamSerializationAllowed = 1;

    // 1) zero counters (PDL: launch overlaps prior replay's tail; stores
    //    gated by gdc_wait inside the kernel).
    {
        cudaLaunchConfig_t cfg = {};
        cfg.gridDim  = dim3((num_tokens + 255) / 256);
        cfg.blockDim = dim3(256);
        cfg.stream   = 0;
        cfg.attrs    = pdl_attr;
        cfg.numAttrs = 1;
        cudaLaunchKernelEx(&cfg, zero_counts_kernel, num_tokens);
    }

    // 2) bucket (PDL after zero)
    {
        cudaLaunchConfig_t cfg = {};
        cfg.gridDim  = dim3((num_rows + 255) / 256);
        cfg.blockDim = dim3(256);
        cfg.stream   = 0;
        cfg.attrs    = pdl_attr;
        cfg.numAttrs = 1;
        cudaLaunchKernelEx(&cfg, bucket_kernel, token_idx, num_rows);
    }

    // 3) combine (PDL after bucket)
    {
        cudaLaunchConfig_t cfg = {};
        cfg.blockDim = dim3(CTHREADS);
        cfg.stream   = 0;
        cfg.attrs    = pdl_attr;
        cfg.numAttrs = 1;
        if (hidden4 == VPT * CTHREADS && (num_tokens % TPB) == 0) {
            cfg.gridDim = dim3(num_tokens / TPB);
            cudaLaunchKernelEx(&cfg, combine_multi_kernel,
                               expert_hidden, token_idx, gates, out);
        } else {
            cfg.gridDim = dim3(num_tokens);
            cudaLaunchKernelEx(&cfg, combine_generic_kernel,
                               expert_hidden, token_idx, gates, out, hidden4);
        }
    }
}